// round 16
// baseline (speedup 1.0000x reference)
#include <cuda_runtime.h>
#include <math.h>
#include <stdint.h>

// Problem constants
#define BB   256          // batch
#define TT   128          // time steps
#define NINW 1024         // obs features
#define HH   512          // H1 == H2
#define EE   256          // GRU hidden
#define AA   16           // action dim
#define MROWS (TT*BB)     // 32768
#define KHE  (EE+AA)      // 272
#define NG   (3*EE)       // 768 (gate width)

// ---------------------------------------------------------------------------
// Device scratch (static __device__ arrays; no allocation anywhere)
// ---------------------------------------------------------------------------
__device__ float  d_X1[MROWS * HH];        // 64 MB
__device__ float  d_X2[MROWS * HH];        // 64 MB
__device__ float  d_GI[MROWS * NG];        // 96 MB  (ir|iz|in per row)
__device__ float  d_AE[TT * BB * AA];      // 2 MB   encoded actions
__device__ float4 d_Wq4[KHE * EE];         // [k][e] -> (whe, wr, wz, wn)
__device__ float4 d_bcg4[EE];              // (bhe, br, bz, bn)
__device__ float  d_Wfold[HH * NG];        // folded W3@Wih   (1.5 MB)
__device__ float  d_bfold[NG];             // folded b3@Wih + bih
__device__ float  d_hx[2][BB * EE];        // ping-pong hidden exchange
__device__ int    d_bar[8];                // per-batch-group barrier counters

__device__ __forceinline__ float* devBuf(int s) {
    switch (s) {
        case 1: return d_X1;
        case 2: return d_X2;
        default: return d_GI;
    }
}

// ---------------------------------------------------------------------------
// Prep: combined recurrent weights  Wq[k][e][g]
// ---------------------------------------------------------------------------
__global__ void prep_wq(const float* __restrict__ Whe, const float* __restrict__ bhe,
                        const float* __restrict__ Whh, const float* __restrict__ bhh) {
    int k = blockIdx.x;
    int e = threadIdx.x;
    const float* wrow = Whe + (size_t)k * EE;
    float s1 = 0.f, s2 = 0.f, s3 = 0.f;
    #pragma unroll 4
    for (int m = 0; m < EE; m++) {
        float w = wrow[m];
        const float* hr = Whh + (size_t)m * NG;
        s1 = fmaf(w, hr[e],          s1);
        s2 = fmaf(w, hr[EE + e],     s2);
        s3 = fmaf(w, hr[2 * EE + e], s3);
    }
    d_Wq4[k * EE + e] = make_float4(wrow[e], s1, s2, s3);

    if (k == 0) {
        float t1 = 0.f, t2 = 0.f, t3 = 0.f;
        #pragma unroll 4
        for (int m = 0; m < EE; m++) {
            float bm = bhe[m];
            const float* hr = Whh + (size_t)m * NG;
            t1 = fmaf(bm, hr[e],          t1);
            t2 = fmaf(bm, hr[EE + e],     t2);
            t3 = fmaf(bm, hr[2 * EE + e], t3);
        }
        d_bcg4[e] = make_float4(bhe[e], t1 + bhh[e], t2 + bhh[EE + e], t3 + bhh[2 * EE + e]);
    }
}

// ---------------------------------------------------------------------------
// Prep: folded MLP tail  Wfold = W3@Wih ; bfold = b3@Wih + bih
// ---------------------------------------------------------------------------
__global__ void prep_fold(const float* __restrict__ W3, const float* __restrict__ b3,
                          const float* __restrict__ Wih, const float* __restrict__ bih) {
    int j = blockIdx.x * 256 + threadIdx.x;   // 0..767
    int k = blockIdx.y;                        // 0..511
    const float* w3row = W3 + (size_t)k * EE;
    float s = 0.f;
    #pragma unroll 4
    for (int m = 0; m < EE; m++)
        s = fmaf(w3row[m], Wih[(size_t)m * NG + j], s);
    d_Wfold[(size_t)k * NG + j] = s;

    if (k == 0) {
        float t = bih[j];
        #pragma unroll 4
        for (int m = 0; m < EE; m++)
            t = fmaf(b3[m], Wih[(size_t)m * NG + j], t);
        d_bfold[j] = t;
    }
}

// ---------------------------------------------------------------------------
// Prep: encoded actions AE[t][b][j] = actions[b][t][:]@Wae + bae
// Also zeroes the gru barrier counters (must be reset every launch/replay).
// ---------------------------------------------------------------------------
__global__ void prep_ae(const float* __restrict__ actions,
                        const float* __restrict__ Wae, const float* __restrict__ bae) {
    if (blockIdx.x == 0 && threadIdx.x < 8) d_bar[threadIdx.x] = 0;
    int gid = blockIdx.x * 256 + threadIdx.x;        // (t*256+b)*16 + j
    int j = gid & 15;
    int b = (gid >> 4) & 255;
    int t = gid >> 12;
    const float* arow = actions + ((size_t)b * TT + t) * AA;
    float s = bae[j];
    #pragma unroll
    for (int k = 0; k < AA; k++) s = fmaf(arow[k], Wae[k * AA + j], s);
    d_AE[gid] = s;
}

// ---------------------------------------------------------------------------
// SGEMM: C[M,N] = A[M,K] @ W[K,N] + bias  (fp32, 128x128x8 tile, 8x8/thread)
// Software-pipelined global->reg->smem. amode==1: obs row remap.
// W==nullptr -> d_Wfold, bias==nullptr -> d_bfold
// ---------------------------------------------------------------------------
__global__ void __launch_bounds__(256, 2)
sgemm_k(const float* __restrict__ Ain, int aSel,
        const float* __restrict__ Win, const float* __restrict__ biasIn,
        int cSel, int M, int N, int K, int amode) {
    __shared__ float As[8][128];
    __shared__ float Bs[8][128];

    const float* A = Ain ? Ain : devBuf(aSel);
    const float* W = Win ? Win : d_Wfold;
    const float* bias = biasIn ? biasIn : d_bfold;
    float* C = devBuf(cSel);

    int tid  = threadIdx.x;
    int row0 = blockIdx.y * 128;
    int col0 = blockIdx.x * 128;
    int tx = tid & 15;
    int ty = tid >> 4;

    int arow = tid >> 1;
    int acol = (tid & 1) * 4;
    const float* Abase;
    if (amode == 1) {
        int tb = row0 + arow;
        int t = tb >> 8, b = tb & 255;
        Abase = A + ((size_t)b * TT + t) * NINW;
    } else {
        Abase = A + (size_t)(row0 + arow) * K;
    }
    int brow = tid >> 5;
    int bcol = (tid & 31) * 4;
    const float* Bbase = W + (size_t)brow * N + col0 + bcol;

    float acc[8][8];
    #pragma unroll
    for (int i = 0; i < 8; i++)
        #pragma unroll
        for (int j = 0; j < 8; j++) acc[i][j] = 0.f;

    {
        float4 av = *(const float4*)(Abase + acol);
        float4 bv = *(const float4*)(Bbase);
        As[acol + 0][arow] = av.x;
        As[acol + 1][arow] = av.y;
        As[acol + 2][arow] = av.z;
        As[acol + 3][arow] = av.w;
        *(float4*)&Bs[brow][bcol] = bv;
    }
    __syncthreads();

    for (int k0 = 0; k0 < K; k0 += 8) {
        bool more = (k0 + 8) < K;
        float4 avn, bvn;
        if (more) {
            avn = *(const float4*)(Abase + k0 + 8 + acol);
            bvn = *(const float4*)(Bbase + (size_t)(k0 + 8) * N);
        }

        #pragma unroll
        for (int kk = 0; kk < 8; kk++) {
            float a[8], bb[8];
            *(float4*)&a[0]  = *(const float4*)&As[kk][ty * 8];
            *(float4*)&a[4]  = *(const float4*)&As[kk][ty * 8 + 4];
            *(float4*)&bb[0] = *(const float4*)&Bs[kk][tx * 8];
            *(float4*)&bb[4] = *(const float4*)&Bs[kk][tx * 8 + 4];
            #pragma unroll
            for (int i = 0; i < 8; i++)
                #pragma unroll
                for (int j = 0; j < 8; j++)
                    acc[i][j] = fmaf(a[i], bb[j], acc[i][j]);
        }

        __syncthreads();
        if (more) {
            As[acol + 0][arow] = avn.x;
            As[acol + 1][arow] = avn.y;
            As[acol + 2][arow] = avn.z;
            As[acol + 3][arow] = avn.w;
            *(float4*)&Bs[brow][bcol] = bvn;
        }
        __syncthreads();
    }

    float bia[8];
    #pragma unroll
    for (int j = 0; j < 8; j++) bia[j] = bias[col0 + tx * 8 + j];

    #pragma unroll
    for (int i = 0; i < 8; i++) {
        size_t r = (size_t)(row0 + ty * 8 + i);
        float* cp = C + r * N + col0 + tx * 8;
        float4 v0 = make_float4(acc[i][0] + bia[0], acc[i][1] + bia[1],
                                acc[i][2] + bia[2], acc[i][3] + bia[3]);
        float4 v1 = make_float4(acc[i][4] + bia[4], acc[i][5] + bia[5],
                                acc[i][6] + bia[6], acc[i][7] + bia[7]);
        *(float4*)(cp)     = v0;
        *(float4*)(cp + 4) = v1;
    }
}

// ---------------------------------------------------------------------------
// Fused per-timestep BatchNorm (training stats over B=256) + ELU, in place.
// ---------------------------------------------------------------------------
__global__ void bn_elu(int sel, const float* __restrict__ g, const float* __restrict__ be) {
    float* X = devBuf(sel);
    int t  = blockIdx.x;
    int jl = threadIdx.x & 63;
    int grp = threadIdx.x >> 6;
    int j = blockIdx.y * 64 + jl;

    float s = 0.f, s2 = 0.f;
    int brow0 = grp * 64;
    #pragma unroll 4
    for (int b = brow0; b < brow0 + 64; b++) {
        float v = X[((size_t)t * BB + b) * HH + j];
        s += v;
        s2 = fmaf(v, v, s2);
    }
    __shared__ float ss[4][64], sq[4][64], mu[64], rs[64];
    ss[grp][jl] = s;
    sq[grp][jl] = s2;
    __syncthreads();
    if (threadIdx.x < 64) {
        float S  = ss[0][jl] + ss[1][jl] + ss[2][jl] + ss[3][jl];
        float S2 = sq[0][jl] + sq[1][jl] + sq[2][jl] + sq[3][jl];
        float m = S * (1.f / 256.f);
        float var = S2 * (1.f / 256.f) - m * m;
        mu[jl] = m;
        rs[jl] = rsqrtf(var + 1e-5f);
    }
    __syncthreads();
    float m = mu[jl], r = rs[jl], gg = g[j], bb = be[j];
    #pragma unroll 4
    for (int b = brow0; b < brow0 + 64; b++) {
        size_t idx = ((size_t)t * BB + b) * HH + j;
        float v = gg * (X[idx] - m) * r + bb;
        X[idx] = v > 0.f ? v : expm1f(v);
    }
}

// ---------------------------------------------------------------------------
// FUSED recurrence, e-sliced for L1-resident weights:
//   grid (8 e-slices, 8 batch-groups) = 64 blocks, 256 threads.
//   Block (es, bg) computes gates for e in [es*32, es*32+32) and batch rows
//   [bg*32, bg*32+32). Its Wq column slice is only 139KB -> stays in L1
//   across all 128 steps (8x less L2 traffic, L1-latency loads).
//   h exchange between the 8 sibling e-slice blocks of a batch group via
//   ping-pong global buffers + per-group monotonic atomic barrier.
//   All 64 blocks are co-resident (grid < #SMs) -> spin barrier is safe.
// ---------------------------------------------------------------------------
__global__ void __launch_bounds__(256, 1)
gru_fused(float* __restrict__ outFinal) {
    __shared__ float hs[32][280];    // [row][k] k<256: h, 256..271: a_prev

    const int tid = threadIdx.x;
    const int el  = tid & 31;        // 0..31 e within slice
    const int rg  = tid >> 5;        // warp id = row group (4 rows)
    const int e   = blockIdx.x * 32 + el;   // global e
    const int b0  = blockIdx.y * 32;        // batch base
    const int grp = blockIdx.y;

    // init h = 0, a_prev = 0
    for (int i = tid; i < 32 * 280; i += 256)
        (&hs[0][0])[i] = 0.f;
    __syncthreads();

    const float4 bc = d_bcg4[e];
    const float4* __restrict__ Wq = d_Wq4;

    for (int t = 0; t < TT; t++) {
        // ---- prefetch this step's GI (independent of h; hides DRAM) ----
        float ir[4], iz[4], inn[4];
        {
            const float* GIt = d_GI + (size_t)t * BB * NG;
            #pragma unroll
            for (int r = 0; r < 4; r++) {
                const float* gi = GIt + (size_t)(b0 + rg * 4 + r) * NG;
                ir[r]  = gi[e];
                iz[r]  = gi[EE + e];
                inn[r] = gi[2 * EE + e];
            }
        }

        // ---- gate GEMM: acc[r] = sum_k hs[row][k] * Wq[k][e] ----
        float4 acc0 = make_float4(0.f, 0.f, 0.f, 0.f);
        float4 acc1 = acc0, acc2 = acc0, acc3 = acc0;

        float4 w0[8], w1[8];
        #pragma unroll
        for (int i = 0; i < 8; i++) w0[i] = Wq[i * EE + e];

        #pragma unroll 1
        for (int kc = 0; kc < KHE / 8; kc++) {          // 34 chunks
            float4* wc = (kc & 1) ? w1 : w0;
            float4* wn = (kc & 1) ? w0 : w1;
            if (kc < KHE / 8 - 1) {
                int kb = (kc + 1) * 8;
                #pragma unroll
                for (int i = 0; i < 8; i++) wn[i] = Wq[(kb + i) * EE + e];
            }
            int kb = kc * 8;
            float h0[4][8];
            #pragma unroll
            for (int r = 0; r < 4; r++) {
                *(float4*)&h0[r][0] = *(const float4*)&hs[rg * 4 + r][kb];
                *(float4*)&h0[r][4] = *(const float4*)&hs[rg * 4 + r][kb + 4];
            }
            #pragma unroll
            for (int i = 0; i < 8; i++) {
                float4 w = wc[i];
                acc0.x = fmaf(h0[0][i], w.x, acc0.x);
                acc0.y = fmaf(h0[0][i], w.y, acc0.y);
                acc0.z = fmaf(h0[0][i], w.z, acc0.z);
                acc0.w = fmaf(h0[0][i], w.w, acc0.w);
                acc1.x = fmaf(h0[1][i], w.x, acc1.x);
                acc1.y = fmaf(h0[1][i], w.y, acc1.y);
                acc1.z = fmaf(h0[1][i], w.z, acc1.z);
                acc1.w = fmaf(h0[1][i], w.w, acc1.w);
                acc2.x = fmaf(h0[2][i], w.x, acc2.x);
                acc2.y = fmaf(h0[2][i], w.y, acc2.y);
                acc2.z = fmaf(h0[2][i], w.z, acc2.z);
                acc2.w = fmaf(h0[2][i], w.w, acc2.w);
                acc3.x = fmaf(h0[3][i], w.x, acc3.x);
                acc3.y = fmaf(h0[3][i], w.y, acc3.y);
                acc3.z = fmaf(h0[3][i], w.z, acc3.z);
                acc3.w = fmaf(h0[3][i], w.w, acc3.w);
            }
        }

        // ---- GRU elementwise ----
        float hnew[4];
        {
            float4 acc[4] = {acc0, acc1, acc2, acc3};
            #pragma unroll
            for (int r = 0; r < 4; r++) {
                float henc = acc[r].x + bc.x;
                float hr   = acc[r].y + bc.y;
                float hz   = acc[r].z + bc.z;
                float hn   = acc[r].w + bc.w;
                float rgt = 1.f / (1.f + expf(-(ir[r] + hr)));
                float zg  = 1.f / (1.f + expf(-(iz[r] + hz)));
                float ng  = tanhf(inn[r] + rgt * hn);
                hnew[r] = (1.f - zg) * ng + zg * henc;
            }
        }

        if (t == TT - 1) {
            #pragma unroll
            for (int r = 0; r < 4; r++)
                outFinal[(size_t)(b0 + rg * 4 + r) * EE + e] = hnew[r];
            break;
        }

        // ---- publish my (rows x e-slice) of h(t+1) ----
        float* hb = d_hx[(t + 1) & 1];
        #pragma unroll
        for (int r = 0; r < 4; r++)
            hb[(size_t)(b0 + rg * 4 + r) * EE + e] = hnew[r];

        __threadfence();
        __syncthreads();
        if (tid == 0) {
            atomicAdd(&d_bar[grp], 1);
            int target = 8 * (t + 1);
            while (atomicAdd(&d_bar[grp], 0) < target) { }
        }
        __syncthreads();
        __threadfence();

        // ---- gather full h(t+1) rows (all 256 e) + AE(t) into smem ----
        // .cg loads bypass L1 (ping-pong buffer may be stale in our L1)
        const float* hbr = d_hx[(t + 1) & 1];
        #pragma unroll
        for (int j = 0; j < 8; j++) {
            int i = tid + j * 256;           // 0..2047
            int row = i >> 6;                // 32 rows
            int c4  = i & 63;                // 64 float4 per row
            float4 v = __ldcg((const float4*)(hbr + (size_t)(b0 + row) * EE) + c4);
            *(float4*)&hs[row][c4 * 4] = v;
        }
        #pragma unroll
        for (int j = 0; j < 2; j++) {
            int i = tid + j * 256;           // 0..511
            int row = i >> 4, c = i & 15;
            hs[row][256 + c] = d_AE[((size_t)t * BB + b0 + row) * AA + c];
        }
        __syncthreads();
    }
}

// ---------------------------------------------------------------------------
// Host launch (graph-capturable: kernel launches only)
// ---------------------------------------------------------------------------
extern "C" void kernel_launch(void* const* d_in, const int* in_sizes, int n_in,
                              void* d_out, int out_size) {
    const float* obs     = (const float*)d_in[0];
    const float* actions = (const float*)d_in[1];
    const float* W1  = (const float*)d_in[2];
    const float* b1  = (const float*)d_in[3];
    const float* g1  = (const float*)d_in[4];
    const float* be1 = (const float*)d_in[5];
    const float* W2  = (const float*)d_in[6];
    const float* b2  = (const float*)d_in[7];
    const float* g2  = (const float*)d_in[8];
    const float* be2 = (const float*)d_in[9];
    const float* W3  = (const float*)d_in[10];
    const float* b3  = (const float*)d_in[11];
    const float* Wih = (const float*)d_in[12];
    const float* bih = (const float*)d_in[13];
    const float* Whh = (const float*)d_in[14];
    const float* bhh = (const float*)d_in[15];
    const float* Whe = (const float*)d_in[16];
    const float* bhe = (const float*)d_in[17];
    const float* Wae = (const float*)d_in[18];
    const float* bae = (const float*)d_in[19];
    float* out = (float*)d_out;

    // One-time-per-launch prep (recomputed every call: deterministic)
    prep_wq<<<KHE, 256>>>(Whe, bhe, Whh, bhh);
    prep_fold<<<dim3(NG / 256, HH), 256>>>(W3, b3, Wih, bih);
    prep_ae<<<(TT * BB * AA) / 256, 256>>>(actions, Wae, bae);

    // Batched MLP + GRU input path (all timesteps in parallel)
    sgemm_k<<<dim3(HH / 128, MROWS / 128), 256>>>(obs, 0, W1, b1, 1, MROWS, HH, NINW, 1);
    bn_elu<<<dim3(TT, HH / 64), 256>>>(1, g1, be1);
    sgemm_k<<<dim3(HH / 128, MROWS / 128), 256>>>(nullptr, 1, W2, b2, 2, MROWS, HH, HH, 0);
    bn_elu<<<dim3(TT, HH / 64), 256>>>(2, g2, be2);
    // Folded (W3@Wih) GEMM: X2 -> GI directly
    sgemm_k<<<dim3(NG / 128, MROWS / 128), 256>>>(nullptr, 2, nullptr, nullptr, 4, MROWS, NG, HH, 0);

    // Entire GRU recurrence in ONE persistent kernel (e-sliced, L1-resident Wq)
    gru_fused<<<dim3(8, 8), 256>>>(out);
}

// round 17
// speedup vs baseline: 1.2040x; 1.2040x over previous
#include <cuda_runtime.h>
#include <math.h>
#include <stdint.h>

// Problem constants
#define BB   256          // batch
#define TT   128          // time steps
#define NINW 1024         // obs features
#define HH   512          // H1 == H2
#define EE   256          // GRU hidden
#define AA   16           // action dim
#define MROWS (TT*BB)     // 32768
#define KHE  (EE+AA)      // 272
#define NG   (3*EE)       // 768 (gate width)

// ---------------------------------------------------------------------------
// Device scratch (static __device__ arrays; no allocation anywhere)
// ---------------------------------------------------------------------------
__device__ float  d_X1[MROWS * HH];        // 64 MB
__device__ float  d_X2[MROWS * HH];        // 64 MB
__device__ float  d_GI[MROWS * NG];        // 96 MB  (ir|iz|in per row)
__device__ float  d_AE[TT * BB * AA];      // 2 MB   encoded actions
__device__ float4 d_Wq4[KHE * EE];         // [k][e] -> (whe, wr, wz, wn)
__device__ float4 d_bcg4[EE];              // (bhe, br, bz, bn)
__device__ float  d_Wfold[HH * NG];        // folded W3@Wih   (1.5 MB)
__device__ float  d_bfold[NG];             // folded b3@Wih + bih

__device__ __forceinline__ float* devBuf(int s) {
    switch (s) {
        case 1: return d_X1;
        case 2: return d_X2;
        default: return d_GI;
    }
}

// ---------------------------------------------------------------------------
// Cluster / DSMEM helpers
// ---------------------------------------------------------------------------
__device__ __forceinline__ uint32_t smem_u32(const void* p) {
    return (uint32_t)__cvta_generic_to_shared(p);
}
__device__ __forceinline__ uint32_t mapa_rank(uint32_t addr, uint32_t rank) {
    uint32_t r;
    asm("mapa.shared::cluster.u32 %0, %1, %2;" : "=r"(r) : "r"(addr), "r"(rank));
    return r;
}
__device__ __forceinline__ float4 ld_cluster_f4(uint32_t addr) {
    float4 v;
    asm volatile("ld.shared::cluster.v4.f32 {%0,%1,%2,%3}, [%4];"
                 : "=f"(v.x), "=f"(v.y), "=f"(v.z), "=f"(v.w) : "r"(addr));
    return v;
}
#define CLUSTER_SYNC() do { \
    asm volatile("barrier.cluster.arrive.aligned;" ::: "memory"); \
    asm volatile("barrier.cluster.wait.aligned;"   ::: "memory"); } while (0)

// ---------------------------------------------------------------------------
// Prep: combined recurrent weights  Wq[k][e][g]
// ---------------------------------------------------------------------------
__global__ void prep_wq(const float* __restrict__ Whe, const float* __restrict__ bhe,
                        const float* __restrict__ Whh, const float* __restrict__ bhh) {
    int k = blockIdx.x;
    int e = threadIdx.x;
    const float* wrow = Whe + (size_t)k * EE;
    float s1 = 0.f, s2 = 0.f, s3 = 0.f;
    #pragma unroll 4
    for (int m = 0; m < EE; m++) {
        float w = wrow[m];
        const float* hr = Whh + (size_t)m * NG;
        s1 = fmaf(w, hr[e],          s1);
        s2 = fmaf(w, hr[EE + e],     s2);
        s3 = fmaf(w, hr[2 * EE + e], s3);
    }
    d_Wq4[k * EE + e] = make_float4(wrow[e], s1, s2, s3);

    if (k == 0) {
        float t1 = 0.f, t2 = 0.f, t3 = 0.f;
        #pragma unroll 4
        for (int m = 0; m < EE; m++) {
            float bm = bhe[m];
            const float* hr = Whh + (size_t)m * NG;
            t1 = fmaf(bm, hr[e],          t1);
            t2 = fmaf(bm, hr[EE + e],     t2);
            t3 = fmaf(bm, hr[2 * EE + e], t3);
        }
        d_bcg4[e] = make_float4(bhe[e], t1 + bhh[e], t2 + bhh[EE + e], t3 + bhh[2 * EE + e]);
    }
}

// ---------------------------------------------------------------------------
// Prep: folded MLP tail  Wfold = W3@Wih ; bfold = b3@Wih + bih
// ---------------------------------------------------------------------------
__global__ void prep_fold(const float* __restrict__ W3, const float* __restrict__ b3,
                          const float* __restrict__ Wih, const float* __restrict__ bih) {
    int j = blockIdx.x * 256 + threadIdx.x;   // 0..767
    int k = blockIdx.y;                        // 0..511
    const float* w3row = W3 + (size_t)k * EE;
    float s = 0.f;
    #pragma unroll 4
    for (int m = 0; m < EE; m++)
        s = fmaf(w3row[m], Wih[(size_t)m * NG + j], s);
    d_Wfold[(size_t)k * NG + j] = s;

    if (k == 0) {
        float t = bih[j];
        #pragma unroll 4
        for (int m = 0; m < EE; m++)
            t = fmaf(b3[m], Wih[(size_t)m * NG + j], t);
        d_bfold[j] = t;
    }
}

// ---------------------------------------------------------------------------
// Prep: encoded actions AE[t][b][j] = actions[b][t][:]@Wae + bae
// ---------------------------------------------------------------------------
__global__ void prep_ae(const float* __restrict__ actions,
                        const float* __restrict__ Wae, const float* __restrict__ bae) {
    int gid = blockIdx.x * 256 + threadIdx.x;        // (t*256+b)*16 + j
    int j = gid & 15;
    int b = (gid >> 4) & 255;
    int t = gid >> 12;
    const float* arow = actions + ((size_t)b * TT + t) * AA;
    float s = bae[j];
    #pragma unroll
    for (int k = 0; k < AA; k++) s = fmaf(arow[k], Wae[k * AA + j], s);
    d_AE[gid] = s;
}

// ---------------------------------------------------------------------------
// SGEMM: C[M,N] = A[M,K] @ W[K,N] + bias  (fp32, 128x128x8 tile, 8x8/thread)
// Software-pipelined global->reg->smem. amode==1: obs row remap.
// W==nullptr -> d_Wfold, bias==nullptr -> d_bfold
// ---------------------------------------------------------------------------
__global__ void __launch_bounds__(256, 2)
sgemm_k(const float* __restrict__ Ain, int aSel,
        const float* __restrict__ Win, const float* __restrict__ biasIn,
        int cSel, int M, int N, int K, int amode) {
    __shared__ float As[8][128];
    __shared__ float Bs[8][128];

    const float* A = Ain ? Ain : devBuf(aSel);
    const float* W = Win ? Win : d_Wfold;
    const float* bias = biasIn ? biasIn : d_bfold;
    float* C = devBuf(cSel);

    int tid  = threadIdx.x;
    int row0 = blockIdx.y * 128;
    int col0 = blockIdx.x * 128;
    int tx = tid & 15;
    int ty = tid >> 4;

    int arow = tid >> 1;
    int acol = (tid & 1) * 4;
    const float* Abase;
    if (amode == 1) {
        int tb = row0 + arow;
        int t = tb >> 8, b = tb & 255;
        Abase = A + ((size_t)b * TT + t) * NINW;
    } else {
        Abase = A + (size_t)(row0 + arow) * K;
    }
    int brow = tid >> 5;
    int bcol = (tid & 31) * 4;
    const float* Bbase = W + (size_t)brow * N + col0 + bcol;

    float acc[8][8];
    #pragma unroll
    for (int i = 0; i < 8; i++)
        #pragma unroll
        for (int j = 0; j < 8; j++) acc[i][j] = 0.f;

    {
        float4 av = *(const float4*)(Abase + acol);
        float4 bv = *(const float4*)(Bbase);
        As[acol + 0][arow] = av.x;
        As[acol + 1][arow] = av.y;
        As[acol + 2][arow] = av.z;
        As[acol + 3][arow] = av.w;
        *(float4*)&Bs[brow][bcol] = bv;
    }
    __syncthreads();

    for (int k0 = 0; k0 < K; k0 += 8) {
        bool more = (k0 + 8) < K;
        float4 avn, bvn;
        if (more) {
            avn = *(const float4*)(Abase + k0 + 8 + acol);
            bvn = *(const float4*)(Bbase + (size_t)(k0 + 8) * N);
        }

        #pragma unroll
        for (int kk = 0; kk < 8; kk++) {
            float a[8], bb[8];
            *(float4*)&a[0]  = *(const float4*)&As[kk][ty * 8];
            *(float4*)&a[4]  = *(const float4*)&As[kk][ty * 8 + 4];
            *(float4*)&bb[0] = *(const float4*)&Bs[kk][tx * 8];
            *(float4*)&bb[4] = *(const float4*)&Bs[kk][tx * 8 + 4];
            #pragma unroll
            for (int i = 0; i < 8; i++)
                #pragma unroll
                for (int j = 0; j < 8; j++)
                    acc[i][j] = fmaf(a[i], bb[j], acc[i][j]);
        }

        __syncthreads();
        if (more) {
            As[acol + 0][arow] = avn.x;
            As[acol + 1][arow] = avn.y;
            As[acol + 2][arow] = avn.z;
            As[acol + 3][arow] = avn.w;
            *(float4*)&Bs[brow][bcol] = bvn;
        }
        __syncthreads();
    }

    float bia[8];
    #pragma unroll
    for (int j = 0; j < 8; j++) bia[j] = bias[col0 + tx * 8 + j];

    #pragma unroll
    for (int i = 0; i < 8; i++) {
        size_t r = (size_t)(row0 + ty * 8 + i);
        float* cp = C + r * N + col0 + tx * 8;
        float4 v0 = make_float4(acc[i][0] + bia[0], acc[i][1] + bia[1],
                                acc[i][2] + bia[2], acc[i][3] + bia[3]);
        float4 v1 = make_float4(acc[i][4] + bia[4], acc[i][5] + bia[5],
                                acc[i][6] + bia[6], acc[i][7] + bia[7]);
        *(float4*)(cp)     = v0;
        *(float4*)(cp + 4) = v1;
    }
}

// ---------------------------------------------------------------------------
// Fused per-timestep BatchNorm (training stats over B=256) + ELU, in place.
// ---------------------------------------------------------------------------
__global__ void bn_elu(int sel, const float* __restrict__ g, const float* __restrict__ be) {
    float* X = devBuf(sel);
    int t  = blockIdx.x;
    int jl = threadIdx.x & 63;
    int grp = threadIdx.x >> 6;
    int j = blockIdx.y * 64 + jl;

    float s = 0.f, s2 = 0.f;
    int brow0 = grp * 64;
    #pragma unroll 4
    for (int b = brow0; b < brow0 + 64; b++) {
        float v = X[((size_t)t * BB + b) * HH + j];
        s += v;
        s2 = fmaf(v, v, s2);
    }
    __shared__ float ss[4][64], sq[4][64], mu[64], rs[64];
    ss[grp][jl] = s;
    sq[grp][jl] = s2;
    __syncthreads();
    if (threadIdx.x < 64) {
        float S  = ss[0][jl] + ss[1][jl] + ss[2][jl] + ss[3][jl];
        float S2 = sq[0][jl] + sq[1][jl] + sq[2][jl] + sq[3][jl];
        float m = S * (1.f / 256.f);
        float var = S2 * (1.f / 256.f) - m * m;
        mu[jl] = m;
        rs[jl] = rsqrtf(var + 1e-5f);
    }
    __syncthreads();
    float m = mu[jl], r = rs[jl], gg = g[j], bb = be[j];
    #pragma unroll 4
    for (int b = brow0; b < brow0 + 64; b++) {
        size_t idx = ((size_t)t * BB + b) * HH + j;
        float v = gg * (X[idx] - m) * r + bb;
        X[idx] = v > 0.f ? v : expm1f(v);
    }
}

// ---------------------------------------------------------------------------
// CLUSTER-FUSED recurrence:
//   grid (8 e-slices, 16 batch-groups) = 128 CTAs, cluster (8,1,1):
//   the 8 e-slice CTAs of one batch group form a cluster.
//   Each CTA: Wq column slice (272 x 32e x 4 gates = 139KB) resident in SMEM,
//   computes gates for its 32 e x 16 rows each step, exchanges h slices via
//   DSMEM reads + one barrier.cluster per step (double-buffered slices).
//   Weight traffic: one-time 18MB total (vs 9GB streamed in R14).
// ---------------------------------------------------------------------------
#define GRU_ROWS 16
#define WS_F4    (KHE * 32)                       // 8704 float4 = 139264 B
#define HBUF_F   (GRU_ROWS * KHE)                 // 16*272 floats
#define HSL_F    (2 * GRU_ROWS * 32)              // double-buffered slices
#define GRU_SMEM ((WS_F4 * 16) + (HBUF_F + HSL_F) * 4)

__global__ void __launch_bounds__(256, 1) __cluster_dims__(8, 1, 1)
gru_cluster(float* __restrict__ outFinal) {
    extern __shared__ float4 smraw[];
    float4* ws   = smraw;                          // [KHE][32] weight slice
    float*  hbuf = (float*)(smraw + WS_F4);        // [16][272] full h|a rows
    float*  hsl  = hbuf + HBUF_F;                  // [2][16][32] my slice

    const int tid = threadIdx.x;
    const int el  = tid & 31;                      // e within slice
    const int wid = tid >> 5;                      // warp -> 2 rows
    const int r0  = wid * 2, r1 = r0 + 1;
    const int es  = blockIdx.x;                    // e-slice / cluster rank
    const int e0  = es * 32;
    const int e   = e0 + el;
    const int b0  = blockIdx.y * GRU_ROWS;

    const uint32_t hsl_base = smem_u32(hsl);

    // ---- prologue: weight slice -> smem, h buffer -> 0 ----
    for (int i = tid; i < WS_F4; i += 256) {
        int k = i >> 5, c = i & 31;
        ws[i] = d_Wq4[k * EE + e0 + c];
    }
    for (int i = tid; i < HBUF_F; i += 256) hbuf[i] = 0.f;
    __syncthreads();

    const float4 bc = d_bcg4[e];

    for (int t = 0; t < TT; t++) {
        const int p = t & 1;
        if (t > 0) {
            // gather all 8 slices of h(t) from cluster peers (incl. self)
            #pragma unroll
            for (int j = 0; j < 4; j++) {
                int i   = tid + j * 256;           // 0..1023
                int c   = i >> 7;                  // peer rank
                int row = (i >> 3) & 15;
                int f4  = i & 7;                   // float4 within 32 floats
                uint32_t laddr = hsl_base + (uint32_t)(((p * GRU_ROWS + row) * 32 + f4 * 4) * 4);
                float4 v = ld_cluster_f4(mapa_rank(laddr, (uint32_t)c));
                *(float4*)&hbuf[row * KHE + c * 32 + f4 * 4] = v;
            }
            // a_prev = AE[t-1]
            if (tid < GRU_ROWS * 4) {
                int row = tid >> 2, f4 = tid & 3;
                *(float4*)&hbuf[row * KHE + EE + f4 * 4] =
                    *(const float4*)&d_AE[(((size_t)(t - 1)) * BB + b0 + row) * AA + f4 * 4];
            }
            __syncthreads();
        }

        // ---- prefetch GI for my (2 rows, e) ----
        float ir[2], iz[2], inn[2];
        #pragma unroll
        for (int r = 0; r < 2; r++) {
            const float* gi = d_GI + ((size_t)t * BB + b0 + r0 + r) * NG;
            ir[r]  = gi[e];
            iz[r]  = gi[EE + e];
            inn[r] = gi[2 * EE + e];
        }

        // ---- gate GEMM from SMEM: acc[r] = sum_k h[r][k] * Wq[k][e] ----
        float4 acc0 = make_float4(0.f, 0.f, 0.f, 0.f);
        float4 acc1 = acc0;
        const float* hp0 = hbuf + r0 * KHE;
        const float* hp1 = hbuf + r1 * KHE;

        #pragma unroll 1
        for (int k = 0; k < KHE; k += 8) {
            float4 w[8];
            #pragma unroll
            for (int i = 0; i < 8; i++) w[i] = ws[(k + i) * 32 + el];
            float h0[8], h1[8];
            *(float4*)&h0[0] = *(const float4*)(hp0 + k);
            *(float4*)&h0[4] = *(const float4*)(hp0 + k + 4);
            *(float4*)&h1[0] = *(const float4*)(hp1 + k);
            *(float4*)&h1[4] = *(const float4*)(hp1 + k + 4);
            #pragma unroll
            for (int i = 0; i < 8; i++) {
                acc0.x = fmaf(h0[i], w[i].x, acc0.x);
                acc0.y = fmaf(h0[i], w[i].y, acc0.y);
                acc0.z = fmaf(h0[i], w[i].z, acc0.z);
                acc0.w = fmaf(h0[i], w[i].w, acc0.w);
                acc1.x = fmaf(h1[i], w[i].x, acc1.x);
                acc1.y = fmaf(h1[i], w[i].y, acc1.y);
                acc1.z = fmaf(h1[i], w[i].z, acc1.z);
                acc1.w = fmaf(h1[i], w[i].w, acc1.w);
            }
        }

        // ---- GRU elementwise ----
        float hnew[2];
        {
            float4 acc[2] = {acc0, acc1};
            #pragma unroll
            for (int r = 0; r < 2; r++) {
                float henc = acc[r].x + bc.x;
                float hr   = acc[r].y + bc.y;
                float hz   = acc[r].z + bc.z;
                float hn   = acc[r].w + bc.w;
                float rg = 1.f / (1.f + expf(-(ir[r] + hr)));
                float zg = 1.f / (1.f + expf(-(iz[r] + hz)));
                float ng = tanhf(inn[r] + rg * hn);
                hnew[r] = (1.f - zg) * ng + zg * henc;
            }
        }

        if (t == TT - 1) {
            outFinal[(size_t)(b0 + r0) * EE + e] = hnew[0];
            outFinal[(size_t)(b0 + r1) * EE + e] = hnew[1];
            break;                                  // uniform across cluster
        }

        // ---- publish my slice of h(t+1), then cluster barrier ----
        const int q = (t + 1) & 1;
        hsl[(q * GRU_ROWS + r0) * 32 + el] = hnew[0];
        hsl[(q * GRU_ROWS + r1) * 32 + el] = hnew[1];
        CLUSTER_SYNC();
    }
}

// ---------------------------------------------------------------------------
// Host launch (graph-capturable: kernel launches only)
// ---------------------------------------------------------------------------
extern "C" void kernel_launch(void* const* d_in, const int* in_sizes, int n_in,
                              void* d_out, int out_size) {
    const float* obs     = (const float*)d_in[0];
    const float* actions = (const float*)d_in[1];
    const float* W1  = (const float*)d_in[2];
    const float* b1  = (const float*)d_in[3];
    const float* g1  = (const float*)d_in[4];
    const float* be1 = (const float*)d_in[5];
    const float* W2  = (const float*)d_in[6];
    const float* b2  = (const float*)d_in[7];
    const float* g2  = (const float*)d_in[8];
    const float* be2 = (const float*)d_in[9];
    const float* W3  = (const float*)d_in[10];
    const float* b3  = (const float*)d_in[11];
    const float* Wih = (const float*)d_in[12];
    const float* bih = (const float*)d_in[13];
    const float* Whh = (const float*)d_in[14];
    const float* bhh = (const float*)d_in[15];
    const float* Whe = (const float*)d_in[16];
    const float* bhe = (const float*)d_in[17];
    const float* Wae = (const float*)d_in[18];
    const float* bae = (const float*)d_in[19];
    float* out = (float*)d_out;

    // Allow big dynamic smem for the cluster kernel (attribute set, no alloc)
    static int smem_set = 0;
    if (!smem_set) {
        cudaFuncSetAttribute(gru_cluster,
                             cudaFuncAttributeMaxDynamicSharedMemorySize, GRU_SMEM);
        smem_set = 1;
    }

    // One-time-per-launch prep (recomputed every call: deterministic)
    prep_wq<<<KHE, 256>>>(Whe, bhe, Whh, bhh);
    prep_fold<<<dim3(NG / 256, HH), 256>>>(W3, b3, Wih, bih);
    prep_ae<<<(TT * BB * AA) / 256, 256>>>(actions, Wae, bae);

    // Batched MLP + GRU input path (all timesteps in parallel)
    sgemm_k<<<dim3(HH / 128, MROWS / 128), 256>>>(obs, 0, W1, b1, 1, MROWS, HH, NINW, 1);
    bn_elu<<<dim3(TT, HH / 64), 256>>>(1, g1, be1);
    sgemm_k<<<dim3(HH / 128, MROWS / 128), 256>>>(nullptr, 1, W2, b2, 2, MROWS, HH, HH, 0);
    bn_elu<<<dim3(TT, HH / 64), 256>>>(2, g2, be2);
    // Folded (W3@Wih) GEMM: X2 -> GI directly
    sgemm_k<<<dim3(NG / 128, MROWS / 128), 256>>>(nullptr, 2, nullptr, nullptr, 4, MROWS, NG, HH, 0);

    // Entire GRU recurrence: 16 clusters of 8 CTAs, SMEM-resident weights,
    // DSMEM h-exchange + barrier.cluster per step.
    gru_cluster<<<dim3(8, 16), 256, GRU_SMEM>>>(out);
}